// round 1
// baseline (speedup 1.0000x reference)
#include <cuda_runtime.h>
#include <math.h>

#define EPSF 1e-6f
#define MAXP 24

static __device__ double g_acc;

__global__ void k_zero_acc() { g_acc = 0.0; }

__global__ void k_finalize(float* out, int N) {
    out[0] = (float)(g_acc / (double)N);
}

__global__ void __launch_bounds__(256) k_ciou(const float* __restrict__ pred,
                                              const float* __restrict__ target,
                                              const float* __restrict__ weight,
                                              int N)
{
    int i = blockIdx.x * blockDim.x + threadIdx.x;
    float contrib = 0.0f;

    if (i < N) {
        const float* P = pred   + (size_t)i * 5;
        const float* T = target + (size_t)i * 5;
        float px = P[0], py = P[1], pw = P[2], ph = P[3], pa = P[4];
        float qx = T[0], qy = T[1], qw = T[2], qh = T[3], qa = T[4];

        // ---- corners (matches box2corners: x4={.5,-.5,-.5,.5}w, y4={.5,.5,-.5,-.5}h) ----
        float c1x[4], c1y[4], c2x[4], c2y[4];
        {
            float c = cosf(pa), s = sinf(pa);
            float hx = 0.5f * pw, hy = 0.5f * ph;
            c1x[0] =  hx*c - hy*s + px;  c1y[0] =  hx*s + hy*c + py;
            c1x[1] = -hx*c - hy*s + px;  c1y[1] = -hx*s + hy*c + py;
            c1x[2] = -hx*c + hy*s + px;  c1y[2] = -hx*s - hy*c + py;
            c1x[3] =  hx*c + hy*s + px;  c1y[3] =  hx*s - hy*c + py;
        }
        {
            float c = cosf(qa), s = sinf(qa);
            float hx = 0.5f * qw, hy = 0.5f * qh;
            c2x[0] =  hx*c - hy*s + qx;  c2y[0] =  hx*s + hy*c + qy;
            c2x[1] = -hx*c - hy*s + qx;  c2y[1] = -hx*s + hy*c + qy;
            c2x[2] = -hx*c + hy*s + qx;  c2y[2] = -hx*s - hy*c + qy;
            c2x[3] =  hx*c + hy*s + qx;  c2y[3] =  hx*s - hy*c + qy;
        }

        float vx[MAXP], vy[MAXP];
        int nv = 0;

        // ---- box_in_box(c1, c2): c1 corners inside c2 (same collect order as ref) ----
        {
            float ax = c2x[0], ay = c2y[0];
            float abx = c2x[1] - ax, aby = c2y[1] - ay;
            float adx = c2x[3] - ax, ady = c2y[3] - ay;
            float dab = fmaxf(abx*abx + aby*aby, EPSF);
            float dad = fmaxf(adx*adx + ady*ady, EPSF);
            #pragma unroll
            for (int k = 0; k < 4; k++) {
                float amx = c1x[k] - ax, amy = c1y[k] - ay;
                float pab = (amx*abx + amy*aby) / dab;
                float pad = (amx*adx + amy*ady) / dad;
                const float tol = 1e-6f;
                if (pab > -tol && pab < 1.0f + tol && pad > -tol && pad < 1.0f + tol) {
                    vx[nv] = c1x[k]; vy[nv] = c1y[k]; nv++;
                }
            }
        }
        // ---- box_in_box(c2, c1) ----
        {
            float ax = c1x[0], ay = c1y[0];
            float abx = c1x[1] - ax, aby = c1y[1] - ay;
            float adx = c1x[3] - ax, ady = c1y[3] - ay;
            float dab = fmaxf(abx*abx + aby*aby, EPSF);
            float dad = fmaxf(adx*adx + ady*ady, EPSF);
            #pragma unroll
            for (int k = 0; k < 4; k++) {
                float amx = c2x[k] - ax, amy = c2y[k] - ay;
                float pab = (amx*abx + amy*aby) / dab;
                float pad = (amx*adx + amy*ady) / dad;
                const float tol = 1e-6f;
                if (pab > -tol && pab < 1.0f + tol && pad > -tol && pad < 1.0f + tol) {
                    vx[nv] = c2x[k]; vy[nv] = c2y[k]; nv++;
                }
            }
        }

        // ---- edge-edge intersections (i-major order, matches reshape(n,16)) ----
        float e1x[4], e1y[4], e2x[4], e2y[4];
        #pragma unroll
        for (int k = 0; k < 4; k++) {
            e1x[k] = c1x[(k+1) & 3] - c1x[k];  e1y[k] = c1y[(k+1) & 3] - c1y[k];
            e2x[k] = c2x[(k+1) & 3] - c2x[k];  e2y[k] = c2y[(k+1) & 3] - c2y[k];
        }
        #pragma unroll
        for (int a = 0; a < 4; a++) {
            #pragma unroll
            for (int b = 0; b < 4; b++) {
                float den = e1x[a]*e2y[b] - e1y[a]*e2x[b];
                if (fabsf(den) > 1e-12f) {
                    float dpx = c2x[b] - c1x[a], dpy = c2y[b] - c1y[a];
                    float t = (dpx*e2y[b] - dpy*e2x[b]) / den;
                    float u = (dpx*e1y[a] - dpy*e1x[a]) / den;
                    if (t > 0.0f && t < 1.0f && u > 0.0f && u < 1.0f) {
                        vx[nv] = c1x[a] + t * e1x[a];
                        vy[nv] = c1y[a] + t * e1y[a];
                        nv++;
                    }
                }
            }
        }

        // ---- mean over valid points (same summation order; interleaved zeros in ref are exact) ----
        float sx = 0.0f, sy = 0.0f;
        for (int k = 0; k < nv; k++) { sx += vx[k]; sy += vy[k]; }
        float denom = (float)(nv > 1 ? nv : 1);
        float mx = sx / denom, my = sy / denom;

        // ---- center, angles, stable insertion sort (matches stable argsort) ----
        float ang[MAXP];
        for (int k = 0; k < nv; k++) {
            vx[k] -= mx; vy[k] -= my;
            ang[k] = atan2f(vy[k], vx[k]);
        }
        for (int a = 1; a < nv; a++) {
            float ka = ang[a], kx = vx[a], ky = vy[a];
            int b = a - 1;
            while (b >= 0 && ang[b] > ka) {
                ang[b+1] = ang[b]; vx[b+1] = vx[b]; vy[b+1] = vy[b];
                b--;
            }
            ang[b+1] = ka; vx[b+1] = kx; vy[b+1] = ky;
        }

        // ---- shoelace: consecutive pairs then wrap term last (ref order) ----
        float area2 = 0.0f;
        for (int k = 0; k + 1 < nv; k++)
            area2 += vx[k]*vy[k+1] - vy[k]*vx[k+1];
        if (nv > 0)
            area2 += vx[nv-1]*vy[0] - vy[nv-1]*vx[0];
        float inter = 0.5f * fabsf(area2);

        // ---- CIoU loss ----
        float a1 = pw * ph;
        float a2 = qw * qh;
        float ious = fmaxf(inter / (a1 + a2 - inter), EPSF);
        float cd = (px - qx)*(px - qx) + (py - qy)*(py - qy);
        float da = atanf(qw / (qh + EPSF)) - atanf(pw / (ph + EPSF));
        float aspect = 0.40528473456935109f * da * da;   // 4/pi^2
        float vterm = aspect / (1.0f - ious + aspect);
        float alpha = vterm / (1.0f - ious + vterm);
        float loss = 1.0f - ious + cd / (pw*pw + ph*ph + EPSF) + alpha * vterm;
        contrib = loss * weight[i];
    }

    // ---- reduction: warp shuffle -> shared -> one double atomic per block ----
    #pragma unroll
    for (int o = 16; o > 0; o >>= 1)
        contrib += __shfl_down_sync(0xffffffffu, contrib, o);

    __shared__ float ws[8];
    int lane = threadIdx.x & 31;
    int wid  = threadIdx.x >> 5;
    if (lane == 0) ws[wid] = contrib;
    __syncthreads();
    if (wid == 0) {
        float s = (lane < 8) ? ws[lane] : 0.0f;
        #pragma unroll
        for (int o = 4; o > 0; o >>= 1)
            s += __shfl_down_sync(0xffu, s, o);
        if (lane == 0)
            atomicAdd(&g_acc, (double)s);
    }
}

extern "C" void kernel_launch(void* const* d_in, const int* in_sizes, int n_in,
                              void* d_out, int out_size)
{
    const float* pred   = (const float*)d_in[0];
    const float* target = (const float*)d_in[1];
    const float* weight = (const float*)d_in[2];
    int N = in_sizes[2];   // weight element count == number of boxes

    k_zero_acc<<<1, 1>>>();
    int threads = 256;
    int blocks = (N + threads - 1) / threads;
    k_ciou<<<blocks, threads>>>(pred, target, weight, N);
    k_finalize<<<1, 1>>>((float*)d_out, N);
}

// round 2
// speedup vs baseline: 1.4562x; 1.4562x over previous
#include <cuda_runtime.h>
#include <math.h>

#define EPSF 1e-6f
#define THREADS 256
#define MAX_BLOCKS 4096

static __device__ float g_partial[MAX_BLOCKS];

__global__ void __launch_bounds__(THREADS) k_ciou(const float* __restrict__ pred,
                                                  const float* __restrict__ target,
                                                  const float* __restrict__ weight,
                                                  int N)
{
    int i = blockIdx.x * THREADS + threadIdx.x;
    float contrib = 0.0f;

    if (i < N) {
        const float* P = pred   + (size_t)i * 5;
        const float* T = target + (size_t)i * 5;
        float px = P[0], py = P[1], pw = P[2], ph = P[3], pa = P[4];
        float qx = T[0], qy = T[1], qw = T[2], qh = T[3], qa = T[4];

        // work in box1-centered coordinates (kills shoelace cancellation)
        float ox = qx - px, oy = qy - py;

        // corners, CCW: k=0..3 -> (+,+),(-,+),(-,-),(+,-) in local frame
        float c2x[4], c2y[4];
        float bx[2][8], by[2][8];   // ping-pong subject polygon buffers
        {
            float c, s;
            __sincosf(pa, &s, &c);
            float hx = 0.5f * pw, hy = 0.5f * ph;
            bx[0][0] =  hx*c - hy*s;  by[0][0] =  hx*s + hy*c;
            bx[0][1] = -hx*c - hy*s;  by[0][1] = -hx*s + hy*c;
            bx[0][2] = -hx*c + hy*s;  by[0][2] = -hx*s - hy*c;
            bx[0][3] =  hx*c + hy*s;  by[0][3] =  hx*s - hy*c;
        }
        {
            float c, s;
            __sincosf(qa, &s, &c);
            float hx = 0.5f * qw, hy = 0.5f * qh;
            c2x[0] =  hx*c - hy*s + ox;  c2y[0] =  hx*s + hy*c + oy;
            c2x[1] = -hx*c - hy*s + ox;  c2y[1] = -hx*s + hy*c + oy;
            c2x[2] = -hx*c + hy*s + ox;  c2y[2] = -hx*s - hy*c + oy;
            c2x[3] =  hx*c + hy*s + ox;  c2y[3] =  hx*s - hy*c + oy;
        }

        // Sutherland–Hodgman: clip box1 against the 4 CCW edges of box2.
        // inside(P) = cross(edge, P - A) >= 0
        int n = 4;
        #pragma unroll
        for (int e = 0; e < 4; e++) {
            const float* inx = bx[e & 1];
            const float* iny = by[e & 1];
            float* outx = bx[(e & 1) ^ 1];
            float* outy = by[(e & 1) ^ 1];
            float ax = c2x[e], ay = c2y[e];
            float ex = c2x[(e + 1) & 3] - ax;
            float ey = c2y[(e + 1) & 3] - ay;
            int m = 0;
            for (int k = 0; k < n; k++) {
                int k2 = (k + 1 == n) ? 0 : k + 1;
                float cx = inx[k],  cy = iny[k];
                float nx = inx[k2], ny = iny[k2];
                float dc = ex * (cy - ay) - ey * (cx - ax);
                float dn = ex * (ny - ay) - ey * (nx - ax);
                bool cin = dc >= 0.0f;
                bool nin = dn >= 0.0f;
                if (cin) { outx[m] = cx; outy[m] = cy; m++; }
                if (cin != nin) {
                    float t = __fdividef(dc, dc - dn);
                    outx[m] = cx + t * (nx - cx);
                    outy[m] = cy + t * (ny - cy);
                    m++;
                }
            }
            n = m;
        }

        // shoelace on final polygon (buffer index 0 after 4 clips: (3&1)^1 = 0)
        const float* fx = bx[0];
        const float* fy = by[0];
        float area2 = 0.0f;
        for (int k = 0; k < n; k++) {
            int k2 = (k + 1 == n) ? 0 : k + 1;
            area2 += fx[k] * fy[k2] - fy[k] * fx[k2];
        }
        float inter = 0.5f * fabsf(area2);

        // CIoU loss
        float a1 = pw * ph;
        float a2 = qw * qh;
        float ious = fmaxf(inter / (a1 + a2 - inter), EPSF);
        float cd = ox * ox + oy * oy;
        float da = atanf(qw / (qh + EPSF)) - atanf(pw / (ph + EPSF));
        float aspect = 0.40528473456935109f * da * da;   // 4/pi^2
        float vterm = aspect / (1.0f - ious + aspect);
        float alpha = vterm / (1.0f - ious + vterm);
        float loss = 1.0f - ious + cd / (pw*pw + ph*ph + EPSF) + alpha * vterm;
        contrib = loss * weight[i];
    }

    // block reduction -> one partial per block (no atomics, no zero kernel)
    #pragma unroll
    for (int o = 16; o > 0; o >>= 1)
        contrib += __shfl_down_sync(0xffffffffu, contrib, o);

    __shared__ float ws[THREADS / 32];
    int lane = threadIdx.x & 31;
    int wid  = threadIdx.x >> 5;
    if (lane == 0) ws[wid] = contrib;
    __syncthreads();
    if (wid == 0) {
        float s = (lane < THREADS / 32) ? ws[lane] : 0.0f;
        #pragma unroll
        for (int o = 4; o > 0; o >>= 1)
            s += __shfl_down_sync(0xffu, s, o);
        if (lane == 0) g_partial[blockIdx.x] = s;
    }
}

__global__ void __launch_bounds__(256) k_finalize(float* __restrict__ out,
                                                  int nblocks, int N)
{
    double acc = 0.0;
    for (int k = threadIdx.x; k < nblocks; k += 256)
        acc += (double)g_partial[k];

    // warp reduce doubles
    #pragma unroll
    for (int o = 16; o > 0; o >>= 1)
        acc += __shfl_down_sync(0xffffffffu, acc, o);

    __shared__ double ws[8];
    int lane = threadIdx.x & 31;
    int wid  = threadIdx.x >> 5;
    if (lane == 0) ws[wid] = acc;
    __syncthreads();
    if (wid == 0) {
        double s = (lane < 8) ? ws[lane] : 0.0;
        #pragma unroll
        for (int o = 4; o > 0; o >>= 1)
            s += __shfl_down_sync(0xffu, s, o);
        if (lane == 0)
            out[0] = (float)(s / (double)N);
    }
}

extern "C" void kernel_launch(void* const* d_in, const int* in_sizes, int n_in,
                              void* d_out, int out_size)
{
    const float* pred   = (const float*)d_in[0];
    const float* target = (const float*)d_in[1];
    const float* weight = (const float*)d_in[2];
    int N = in_sizes[2];   // weight element count == number of boxes

    int blocks = (N + THREADS - 1) / THREADS;
    k_ciou<<<blocks, THREADS>>>(pred, target, weight, N);
    k_finalize<<<1, 256>>>((float*)d_out, blocks, N);
}

// round 3
// speedup vs baseline: 3.5534x; 2.4401x over previous
#include <cuda_runtime.h>
#include <math.h>

#define EPSF 1e-6f
#define THREADS 256
#define MAX_BLOCKS 8192

static __device__ float g_partial[MAX_BLOCKS];
static __device__ unsigned int g_done;   // zero-init at load; reset in-kernel each run

// Liang–Barsky clip of segment A + t*D (t in [0,1]) against the box
// |s_u| <= hu, |s_v| <= hv, where s_u/s_v are the segment endpoints'
// coordinates along the box axes. Returns the Green's-theorem line
// integral of x dy over the clipped sub-segment (0 if empty).
__device__ __forceinline__ float clip_integral(
    float ax, float ay, float dx, float dy,
    float su0, float su1, float sv0, float sv1,
    float hu, float hv)
{
    float du = su1 - su0;
    float ru = __fdividef(1.0f, du);
    float tA = (hu - su0) * ru;          // crossing of s_u = +hu
    float tB = -(hu + su0) * ru;         // crossing of s_u = -hu
    float t0 = fmaxf(0.0f, fminf(tA, tB));
    float t1 = fminf(1.0f, fmaxf(tA, tB));

    float dv = sv1 - sv0;
    float rv = __fdividef(1.0f, dv);
    float tC = (hv - sv0) * rv;
    float tD = -(hv + sv0) * rv;
    t0 = fmaxf(t0, fminf(tC, tD));
    t1 = fminf(t1, fmaxf(tC, tD));

    float dt = t1 - t0;
    float c = dy * (ax * dt + 0.5f * dx * (t1 + t0) * dt);
    return (dt > 0.0f) ? c : 0.0f;
}

__global__ void __launch_bounds__(THREADS) k_ciou(const float* __restrict__ pred,
                                                  const float* __restrict__ target,
                                                  const float* __restrict__ weight,
                                                  float* __restrict__ out,
                                                  int N)
{
    int i = blockIdx.x * THREADS + threadIdx.x;
    float contrib = 0.0f;

    if (i < N) {
        const float* P = pred   + (size_t)i * 5;
        const float* T = target + (size_t)i * 5;
        float px = P[0], py = P[1], pw = P[2], ph = P[3], pa = P[4];
        float qx = T[0], qy = T[1], qw = T[2], qh = T[3], qa = T[4];

        // all geometry relative to pred center (conditioning)
        float ox = qx - px, oy = qy - py;

        float cp, sp, cq, sq;
        __sincosf(pa, &sp, &cp);
        __sincosf(qa, &sq, &cq);
        float hw1 = 0.5f * pw, hh1 = 0.5f * ph;
        float hw2 = 0.5f * qw, hh2 = 0.5f * qh;

        // CCW corners: (+,+), (-,+), (-,-), (+,-) in each local frame
        float p1x[4], p1y[4], p2x[4], p2y[4];
        {
            float ux = hw1 * cp, uy = hw1 * sp;      // half-extent along box1 u-axis
            float vx = -hh1 * sp, vy = hh1 * cp;     // half-extent along box1 v-axis
            p1x[0] =  ux + vx;  p1y[0] =  uy + vy;
            p1x[1] = -ux + vx;  p1y[1] = -uy + vy;
            p1x[2] = -ux - vx;  p1y[2] = -uy - vy;
            p1x[3] =  ux - vx;  p1y[3] =  uy - vy;
        }
        {
            float ux = hw2 * cq, uy = hw2 * sq;
            float vx = -hh2 * sq, vy = hh2 * cq;
            p2x[0] =  ux + vx + ox;  p2y[0] =  uy + vy + oy;
            p2x[1] = -ux + vx + ox;  p2y[1] = -uy + vy + oy;
            p2x[2] = -ux - vx + ox;  p2y[2] = -uy - vy + oy;
            p2x[3] =  ux - vx + ox;  p2y[3] =  uy - vy + oy;
        }

        // box1 corners in box2's axis frame; box2 corners in box1's frame
        float su[4], sv[4], tu[4], tv[4];
        #pragma unroll
        for (int k = 0; k < 4; k++) {
            float rx = p1x[k] - ox, ry = p1y[k] - oy;
            su[k] =  rx * cq + ry * sq;      // along box2 u
            sv[k] = -rx * sq + ry * cq;      // along box2 v
            tu[k] =  p2x[k] * cp + p2y[k] * sp;   // box2 corner along box1 u
            tv[k] = -p2x[k] * sp + p2y[k] * cp;
        }

        // Green's theorem: sum ∮ x dy over boundary of intersection
        float area = 0.0f;
        #pragma unroll
        for (int k = 0; k < 4; k++) {
            int k2 = (k + 1) & 3;
            area += clip_integral(p1x[k], p1y[k],
                                  p1x[k2] - p1x[k], p1y[k2] - p1y[k],
                                  su[k], su[k2], sv[k], sv[k2], hw2, hh2);
        }
        #pragma unroll
        for (int k = 0; k < 4; k++) {
            int k2 = (k + 1) & 3;
            area += clip_integral(p2x[k], p2y[k],
                                  p2x[k2] - p2x[k], p2y[k2] - p2y[k],
                                  tu[k], tu[k2], tv[k], tv[k2], hw1, hh1);
        }
        float inter = fabsf(area);

        // CIoU loss
        float a1 = pw * ph;
        float a2 = qw * qh;
        float ious = fmaxf(inter / (a1 + a2 - inter), EPSF);
        float cd = ox * ox + oy * oy;
        float da = atanf(qw / (qh + EPSF)) - atanf(pw / (ph + EPSF));
        float aspect = 0.40528473456935109f * da * da;   // 4/pi^2
        float vterm = aspect / (1.0f - ious + aspect);
        float alpha = vterm / (1.0f - ious + vterm);
        float loss = 1.0f - ious + cd / (pw * pw + ph * ph + EPSF) + alpha * vterm;
        contrib = loss * weight[i];
    }

    // ---- block reduction ----
    #pragma unroll
    for (int o = 16; o > 0; o >>= 1)
        contrib += __shfl_down_sync(0xffffffffu, contrib, o);

    __shared__ float ws[THREADS / 32];
    __shared__ bool is_last;
    int lane = threadIdx.x & 31;
    int wid  = threadIdx.x >> 5;
    if (lane == 0) ws[wid] = contrib;
    __syncthreads();
    if (wid == 0) {
        float s = (lane < THREADS / 32) ? ws[lane] : 0.0f;
        #pragma unroll
        for (int o = 4; o > 0; o >>= 1)
            s += __shfl_down_sync(0xffu, s, o);
        if (lane == 0) {
            g_partial[blockIdx.x] = s;
            __threadfence();
            unsigned int t = atomicAdd(&g_done, 1u);
            is_last = (t == gridDim.x - 1);
        }
    }
    __syncthreads();

    // ---- last block finishes: reduce partials, write mean, reset counter ----
    if (is_last) {
        int nblocks = gridDim.x;
        double acc = 0.0;
        for (int k = threadIdx.x; k < nblocks; k += THREADS)
            acc += (double)g_partial[k];

        #pragma unroll
        for (int o = 16; o > 0; o >>= 1)
            acc += __shfl_down_sync(0xffffffffu, acc, o);

        __shared__ double wd[THREADS / 32];
        if (lane == 0) wd[wid] = acc;
        __syncthreads();
        if (wid == 0) {
            double s = (lane < THREADS / 32) ? wd[lane] : 0.0;
            #pragma unroll
            for (int o = 4; o > 0; o >>= 1)
                s += __shfl_down_sync(0xffu, s, o);
            if (lane == 0) {
                out[0] = (float)(s / (double)N);
                g_done = 0;            // reset for next graph replay
            }
        }
    }
}

extern "C" void kernel_launch(void* const* d_in, const int* in_sizes, int n_in,
                              void* d_out, int out_size)
{
    const float* pred   = (const float*)d_in[0];
    const float* target = (const float*)d_in[1];
    const float* weight = (const float*)d_in[2];
    int N = in_sizes[2];   // weight element count == number of boxes

    int blocks = (N + THREADS - 1) / THREADS;
    k_ciou<<<blocks, THREADS>>>(pred, target, weight, (float*)d_out, N);
}

// round 4
// speedup vs baseline: 3.5768x; 1.0066x over previous
#include <cuda_runtime.h>
#include <math.h>

#define EPSF 1e-6f
#define THREADS 256
#define MAX_BLOCKS 8192

static __device__ float g_partial[MAX_BLOCKS];
static __device__ unsigned int g_done;   // zero-init; reset in-kernel each run

// minimax atan on [0,1], extended to x>=0 via atan(x) = pi/2 - atan(1/x).
// max abs error ~1e-5 rad.
__device__ __forceinline__ float fast_atan_pos(float x)
{
    bool inv = x > 1.0f;
    float t = inv ? __fdividef(1.0f, x) : x;
    float t2 = t * t;
    float p = fmaf(t2, 0.0208351f, -0.0851330f);
    p = fmaf(t2, p, 0.1801410f);
    p = fmaf(t2, p, -0.3302995f);
    p = fmaf(t2, p, 0.9998660f);
    float r = t * p;
    return inv ? (1.5707963267948966f - r) : r;
}

// Liang–Barsky clip of segment A + t*D (t in [0,1]) against |s_u|<=hu, |s_v|<=hv.
// Returns Green's line integral of x dy over the clipped sub-segment.
__device__ __forceinline__ float clip_integral(
    float ax, float dx, float dy,
    float su0, float su1, float sv0, float sv1,
    float hu, float hv)
{
    float ru = __fdividef(1.0f, su1 - su0);
    float tA = (hu - su0) * ru;
    float tB = -(hu + su0) * ru;
    float t0 = fmaxf(0.0f, fminf(tA, tB));
    float t1 = fminf(1.0f, fmaxf(tA, tB));

    float rv = __fdividef(1.0f, sv1 - sv0);
    float tC = (hv - sv0) * rv;
    float tD = -(hv + sv0) * rv;
    t0 = fmaxf(t0, fminf(tC, tD));
    t1 = fminf(t1, fmaxf(tC, tD));

    float dt = t1 - t0;
    float c = dy * fmaf(0.5f * dx, (t1 + t0) * dt, ax * dt);
    return (dt > 0.0f) ? c : 0.0f;
}

__global__ void __launch_bounds__(THREADS) k_ciou(const float* __restrict__ pred,
                                                  const float* __restrict__ target,
                                                  const float* __restrict__ weight,
                                                  float* __restrict__ out,
                                                  int N)
{
    __shared__ float spred[THREADS * 5];
    __shared__ float starg[THREADS * 5];

    int base = blockIdx.x * THREADS;
    int cnt = min(THREADS, N - base);            // boxes handled by this block
    int nf = cnt * 5;

    // coalesced float4 staging (base*5 floats is 16B-aligned: 1280*blockIdx)
    {
        const float4* gp4 = (const float4*)(pred   + (size_t)base * 5);
        const float4* gt4 = (const float4*)(target + (size_t)base * 5);
        float4* sp4 = (float4*)spred;
        float4* st4 = (float4*)starg;
        int nf4 = nf >> 2;
        for (int j = threadIdx.x; j < nf4; j += THREADS) {
            sp4[j] = gp4[j];
            st4[j] = gt4[j];
        }
        const float* gp = pred   + (size_t)base * 5;
        const float* gt = target + (size_t)base * 5;
        for (int j = (nf4 << 2) + threadIdx.x; j < nf; j += THREADS) {
            spred[j] = gp[j];
            starg[j] = gt[j];
        }
    }
    __syncthreads();

    int i = base + threadIdx.x;
    float contrib = 0.0f;

    if (i < N) {
        const float* P = spred + threadIdx.x * 5;
        const float* T = starg + threadIdx.x * 5;
        float px = P[0], py = P[1], pw = P[2], ph = P[3], pa = P[4];
        float qx = T[0], qy = T[1], qw = T[2], qh = T[3], qa = T[4];

        float ox = qx - px, oy = qy - py;        // pred-centered frame

        float cp, sp, cq, sq;
        __sincosf(pa, &sp, &cp);
        __sincosf(qa, &sq, &cq);
        float hw1 = 0.5f * pw, hh1 = 0.5f * ph;
        float hw2 = 0.5f * qw, hh2 = 0.5f * qh;

        // relative rotation r = pa - qa
        float cr = cp * cq + sp * sq;
        float sr = sp * cq - cp * sq;

        // world-frame corners, CCW: (+,+),(-,+),(-,-),(+,-)
        float p1x[4], p1y[4], p2x[4], p2y[4];
        {
            float ux = hw1 * cp, uy = hw1 * sp;
            float vx = -hh1 * sp, vy = hh1 * cp;
            p1x[0] =  ux + vx;  p1y[0] =  uy + vy;
            p1x[1] = -ux + vx;  p1y[1] = -uy + vy;
            p1x[2] = -ux - vx;  p1y[2] = -uy - vy;
            p1x[3] =  ux - vx;  p1y[3] =  uy - vy;
        }
        {
            float ux = hw2 * cq, uy = hw2 * sq;
            float vx = -hh2 * sq, vy = hh2 * cq;
            p2x[0] =  ux + vx + ox;  p2y[0] =  uy + vy + oy;
            p2x[1] = -ux + vx + ox;  p2y[1] = -uy + vy + oy;
            p2x[2] = -ux - vx + ox;  p2y[2] = -uy - vy + oy;
            p2x[3] =  ux - vx + ox;  p2y[3] =  uy - vy + oy;
        }

        // box1 corners in box2's frame: su = cr*x - sr*y + du, sv = sr*x + cr*y + dv
        float du = -(ox * cq + oy * sq);
        float dv =  (ox * sq - oy * cq);
        float A = cr * hw1, B = sr * hh1, C = sr * hw1, D = cr * hh1;
        float su[4], sv[4];
        su[0] =  A - B + du;  sv[0] =  C + D + dv;
        su[1] = -A - B + du;  sv[1] = -C + D + dv;
        su[2] = -A + B + du;  sv[2] = -C - D + dv;
        su[3] =  A + B + du;  sv[3] =  C - D + dv;

        // box2 corners in box1's frame: tu = cr*x + sr*y + eu, tv = -sr*x + cr*y + ev
        float eu =  ox * cp + oy * sp;
        float ev = -ox * sp + oy * cp;
        float E = cr * hw2, F = sr * hh2, G = sr * hw2, H = cr * hh2;
        float tu[4], tv[4];
        tu[0] =  E + F + eu;  tv[0] = -G + H + ev;
        tu[1] = -E + F + eu;  tv[1] =  G + H + ev;
        tu[2] = -E - F + eu;  tv[2] =  G - H + ev;
        tu[3] =  E - F + eu;  tv[3] = -G - H + ev;

        // Green's theorem: sum of ∮ x dy over intersection boundary
        float area = 0.0f;
        #pragma unroll
        for (int k = 0; k < 4; k++) {
            int k2 = (k + 1) & 3;
            area += clip_integral(p1x[k],
                                  p1x[k2] - p1x[k], p1y[k2] - p1y[k],
                                  su[k], su[k2], sv[k], sv[k2], hw2, hh2);
        }
        #pragma unroll
        for (int k = 0; k < 4; k++) {
            int k2 = (k + 1) & 3;
            area += clip_integral(p2x[k],
                                  p2x[k2] - p2x[k], p2y[k2] - p2y[k],
                                  tu[k], tu[k2], tv[k], tv[k2], hw1, hh1);
        }
        float inter = fabsf(area);

        // CIoU loss (fast divides; rel-err budget is 1e-3)
        float a1 = pw * ph;
        float a2 = qw * qh;
        float ious = fmaxf(__fdividef(inter, a1 + a2 - inter), EPSF);
        float cd = ox * ox + oy * oy;
        float da = fast_atan_pos(__fdividef(qw, qh + EPSF))
                 - fast_atan_pos(__fdividef(pw, ph + EPSF));
        float aspect = 0.40528473456935109f * da * da;   // 4/pi^2
        float omi = 1.0f - ious;
        float vterm = __fdividef(aspect, omi + aspect);
        float alpha = __fdividef(vterm, omi + vterm);
        float loss = omi + __fdividef(cd, pw * pw + ph * ph + EPSF) + alpha * vterm;
        contrib = loss * weight[i];
    }

    // ---- block reduction ----
    #pragma unroll
    for (int o = 16; o > 0; o >>= 1)
        contrib += __shfl_down_sync(0xffffffffu, contrib, o);

    __shared__ float ws[THREADS / 32];
    __shared__ bool is_last;
    int lane = threadIdx.x & 31;
    int wid  = threadIdx.x >> 5;
    if (lane == 0) ws[wid] = contrib;
    __syncthreads();
    if (wid == 0) {
        float s = (lane < THREADS / 32) ? ws[lane] : 0.0f;
        #pragma unroll
        for (int o = 4; o > 0; o >>= 1)
            s += __shfl_down_sync(0xffu, s, o);
        if (lane == 0) {
            g_partial[blockIdx.x] = s;
            __threadfence();
            unsigned int t = atomicAdd(&g_done, 1u);
            is_last = (t == gridDim.x - 1);
        }
    }
    __syncthreads();

    // ---- last block: reduce partials, write mean, reset counter ----
    if (is_last) {
        int nblocks = gridDim.x;
        double acc = 0.0;
        for (int k = threadIdx.x; k < nblocks; k += THREADS)
            acc += (double)g_partial[k];

        #pragma unroll
        for (int o = 16; o > 0; o >>= 1)
            acc += __shfl_down_sync(0xffffffffu, acc, o);

        __shared__ double wd[THREADS / 32];
        if (lane == 0) wd[wid] = acc;
        __syncthreads();
        if (wid == 0) {
            double s = (lane < THREADS / 32) ? wd[lane] : 0.0;
            #pragma unroll
            for (int o = 4; o > 0; o >>= 1)
                s += __shfl_down_sync(0xffu, s, o);
            if (lane == 0) {
                out[0] = (float)(s / (double)N);
                g_done = 0;
            }
        }
    }
}

extern "C" void kernel_launch(void* const* d_in, const int* in_sizes, int n_in,
                              void* d_out, int out_size)
{
    const float* pred   = (const float*)d_in[0];
    const float* target = (const float*)d_in[1];
    const float* weight = (const float*)d_in[2];
    int N = in_sizes[2];

    int blocks = (N + THREADS - 1) / THREADS;
    k_ciou<<<blocks, THREADS>>>(pred, target, weight, (float*)d_out, N);
}

// round 5
// speedup vs baseline: 4.4808x; 1.2527x over previous
#include <cuda_runtime.h>
#include <math.h>

#define EPSF 1e-6f
#define THREADS 256
#define MAX_BLOCKS 8192

static __device__ float g_partial[MAX_BLOCKS];
static __device__ unsigned int g_done;   // zero-init; reset in-kernel each run

// minimax atan on [0,1], extended to x>=0 via atan(x) = pi/2 - atan(1/x).
__device__ __forceinline__ float fast_atan_pos(float x)
{
    bool inv = x > 1.0f;
    float t = inv ? __fdividef(1.0f, x) : x;
    float t2 = t * t;
    float p = fmaf(t2, 0.0208351f, -0.0851330f);
    p = fmaf(t2, p, 0.1801410f);
    p = fmaf(t2, p, -0.3302995f);
    p = fmaf(t2, p, 0.9998660f);
    float r = t * p;
    return inv ? (1.5707963267948966f - r) : r;
}

// Liang–Barsky window length for segment with endpoint coords (u0,v0)->(u1,v1)
// against |u|<=hu, |v|<=hv. Returns (t0, t1) via out params; valid iff t1>t0.
__device__ __forceinline__ void clip_window(
    float u0, float u1, float v0, float v1,
    float hu, float hv, float& t0, float& t1)
{
    float ru = __fdividef(1.0f, u1 - u0);
    float tA = (hu - u0) * ru;
    float tB = -(hu + u0) * ru;
    t0 = fmaxf(0.0f, fminf(tA, tB));
    t1 = fminf(1.0f, fmaxf(tA, tB));

    float rv = __fdividef(1.0f, v1 - v0);
    float tC = (hv - v0) * rv;
    float tD = -(hv + v0) * rv;
    t0 = fmaxf(t0, fminf(tC, tD));
    t1 = fminf(t1, fmaxf(tC, tD));
}

// Green's ∫x dy over the clipped part of segment (u0,v0)->(u1,v1),
// clipped against |u|<=hu, |v|<=hv (same coords are integrand and clip frame).
__device__ __forceinline__ float clip_integral(
    float u0, float u1, float v0, float v1, float hu, float hv)
{
    float t0, t1;
    clip_window(u0, u1, v0, v1, hu, hv, t0, t1);
    float dt = t1 - t0;
    float c = (v1 - v0) * fmaf(0.5f * (u1 - u0), (t1 + t0) * dt, u0 * dt);
    return (dt > 0.0f) ? c : 0.0f;
}

// clipped length fraction only (for box1's own vertical edges)
__device__ __forceinline__ float clip_dt(
    float u0, float u1, float v0, float v1, float hu, float hv)
{
    float t0, t1;
    clip_window(u0, u1, v0, v1, hu, hv, t0, t1);
    return fmaxf(t1 - t0, 0.0f);
}

__global__ void __launch_bounds__(THREADS) k_ciou(const float* __restrict__ pred,
                                                  const float* __restrict__ target,
                                                  const float* __restrict__ weight,
                                                  float* __restrict__ out,
                                                  int N)
{
    int i = blockIdx.x * THREADS + threadIdx.x;
    float contrib = 0.0f;

    if (i < N) {
        const float* P = pred   + (size_t)i * 5;
        const float* T = target + (size_t)i * 5;
        float px = P[0], py = P[1], pw = P[2], ph = P[3], pa = P[4];
        float qx = T[0], qy = T[1], qw = T[2], qh = T[3], qa = T[4];
        float w  = weight[i];

        float ox = qx - px, oy = qy - py;

        float cp, sp, cq, sq;
        __sincosf(pa, &sp, &cp);
        __sincosf(qa, &sq, &cq);
        float hw1 = 0.5f * pw, hh1 = 0.5f * ph;
        float hw2 = 0.5f * qw, hh2 = 0.5f * qh;

        // relative rotation r = pa - qa
        float cr = fmaf(cp, cq,  sp * sq);
        float sr = fmaf(sp, cq, -cp * sq);

        // box2 corners in box1's frame (CCW preserved):
        // (u2,v2) -> ( cr*u2 + sr*v2 + eu, -sr*u2 + cr*v2 + ev )
        float eu = fmaf(ox, cp,  oy * sp);
        float ev = fmaf(-ox, sp, oy * cp);
        float E = cr * hw2, F = sr * hh2, G = sr * hw2, H = cr * hh2;
        float tu[4], tv[4];
        tu[0] =  E + F + eu;  tv[0] = -G + H + ev;
        tu[1] = -E + F + eu;  tv[1] =  G + H + ev;
        tu[2] = -E - F + eu;  tv[2] =  G - H + ev;
        tu[3] =  E - F + eu;  tv[3] = -G - H + ev;

        // box1 corners in box2's frame:
        // (u1,v1) -> ( cr*u1 - sr*v1 + du, sr*u1 + cr*v1 + dv )
        float du = -fmaf(ox, cq,  oy * sq);
        float dv =  fmaf(ox, sq, -oy * cq);
        float A = cr * hw1, B = sr * hh1, C = sr * hw1, D = cr * hh1;
        float su[4], sv[4];
        su[0] =  A - B + du;  sv[0] =  C + D + dv;
        su[1] = -A - B + du;  sv[1] = -C + D + dv;
        su[2] = -A + B + du;  sv[2] = -C - D + dv;
        su[3] =  A + B + du;  sv[3] =  C - D + dv;

        // Green's theorem in box1's frame.
        // box2's 4 edges: full integrand, clipped against |u|<=hw1,|v|<=hh1.
        float area = 0.0f;
        #pragma unroll
        for (int k = 0; k < 4; k++) {
            int k2 = (k + 1) & 3;
            area += clip_integral(tu[k], tu[k2], tv[k], tv[k2], hw1, hh1);
        }
        // box1's horizontal edges: dy = 0 -> no contribution.
        // box1's vertical edges (x = -hw1 going down, x = +hw1 going up):
        // each contributes 2*hw1*hh1*dt, clipped against box2.
        float dt13 = clip_dt(su[1], su[2], sv[1], sv[2], hw2, hh2)
                   + clip_dt(su[3], su[0], sv[3], sv[0], hw2, hh2);
        area = fmaf(2.0f * hw1 * hh1, dt13, area);

        float inter = fabsf(area);

        // CIoU loss
        float a1 = pw * ph;
        float a2 = qw * qh;
        float ious = fmaxf(__fdividef(inter, a1 + a2 - inter), EPSF);
        float cd = fmaf(ox, ox, oy * oy);

        // atan(qw/(qh+e)) - atan(pw/(ph+e)) = atan(num/den); only da^2 is used
        float num = fmaf(qw, ph + EPSF, -pw * (qh + EPSF));
        float den = fmaf(qh + EPSF, ph + EPSF, qw * pw);
        float da = fast_atan_pos(fabsf(__fdividef(num, den)));
        float aspect = 0.40528473456935109f * da * da;   // 4/pi^2

        float omi = 1.0f - ious;
        float vterm = __fdividef(aspect, omi + aspect);
        float alpha = __fdividef(vterm, omi + vterm);
        float loss = omi + __fdividef(cd, fmaf(pw, pw, ph * ph) + EPSF)
                   + alpha * vterm;
        contrib = loss * w;
    }

    // ---- block reduction ----
    #pragma unroll
    for (int o = 16; o > 0; o >>= 1)
        contrib += __shfl_down_sync(0xffffffffu, contrib, o);

    __shared__ float ws[THREADS / 32];
    __shared__ bool is_last;
    int lane = threadIdx.x & 31;
    int wid  = threadIdx.x >> 5;
    if (lane == 0) ws[wid] = contrib;
    __syncthreads();
    if (wid == 0) {
        float s = (lane < THREADS / 32) ? ws[lane] : 0.0f;
        #pragma unroll
        for (int o = 4; o > 0; o >>= 1)
            s += __shfl_down_sync(0xffu, s, o);
        if (lane == 0) {
            g_partial[blockIdx.x] = s;
            __threadfence();
            unsigned int t = atomicAdd(&g_done, 1u);
            is_last = (t == gridDim.x - 1);
        }
    }
    __syncthreads();

    // ---- last block: reduce partials, write mean, reset counter ----
    if (is_last) {
        int nblocks = gridDim.x;
        double acc = 0.0;
        for (int k = threadIdx.x; k < nblocks; k += THREADS)
            acc += (double)g_partial[k];

        #pragma unroll
        for (int o = 16; o > 0; o >>= 1)
            acc += __shfl_down_sync(0xffffffffu, acc, o);

        __shared__ double wd[THREADS / 32];
        if (lane == 0) wd[wid] = acc;
        __syncthreads();
        if (wid == 0) {
            double s = (lane < THREADS / 32) ? wd[lane] : 0.0;
            #pragma unroll
            for (int o = 4; o > 0; o >>= 1)
                s += __shfl_down_sync(0xffu, s, o);
            if (lane == 0) {
                out[0] = (float)(s / (double)N);
                g_done = 0;
            }
        }
    }
}

extern "C" void kernel_launch(void* const* d_in, const int* in_sizes, int n_in,
                              void* d_out, int out_size)
{
    const float* pred   = (const float*)d_in[0];
    const float* target = (const float*)d_in[1];
    const float* weight = (const float*)d_in[2];
    int N = in_sizes[2];

    int blocks = (N + THREADS - 1) / THREADS;
    k_ciou<<<blocks, THREADS>>>(pred, target, weight, (float*)d_out, N);
}

// round 6
// speedup vs baseline: 5.4367x; 1.2133x over previous
#include <cuda_runtime.h>
#include <math.h>

#define EPSF 1e-6f
#define THREADS 256
#define BOXES_PER_THREAD 2
#define MAX_BLOCKS 8192

static __device__ float g_partial[MAX_BLOCKS];
static __device__ unsigned int g_done;   // zero-init; reset in-kernel each run

// minimax atan on [0,1], extended via atan(x) = pi/2 - atan(1/x).
__device__ __forceinline__ float fast_atan_pos(float x)
{
    bool inv = x > 1.0f;
    float t = inv ? __fdividef(1.0f, x) : x;
    float t2 = t * t;
    float p = fmaf(t2, 0.0208351f, -0.0851330f);
    p = fmaf(t2, p, 0.1801410f);
    p = fmaf(t2, p, -0.3302995f);
    p = fmaf(t2, p, 0.9998660f);
    float r = t * p;
    return inv ? (1.5707963267948966f - r) : r;
}

// Liang–Barsky window (precomputed reciprocals of the edge deltas).
__device__ __forceinline__ void clip_window(
    float u0, float ru, float v0, float rv,
    float hu, float hv, float& t0, float& t1)
{
    float tA = (hu - u0) * ru;
    float tB = -(hu + u0) * ru;
    t0 = fmaxf(0.0f, fminf(tA, tB));
    t1 = fminf(1.0f, fmaxf(tA, tB));
    float tC = (hv - v0) * rv;
    float tD = -(hv + v0) * rv;
    t0 = fmaxf(t0, fminf(tC, tD));
    t1 = fminf(t1, fmaxf(tC, tD));
}

// Green's ∫x dy over the clipped part of segment starting (u0,v0), delta (du,dv).
__device__ __forceinline__ float clip_integral(
    float u0, float du, float ru, float v0, float dv, float rv,
    float hu, float hv)
{
    float t0, t1;
    clip_window(u0, ru, v0, rv, hu, hv, t0, t1);
    float dt = t1 - t0;
    float c = dv * fmaf(0.5f * du, (t1 + t0) * dt, u0 * dt);
    return (dt > 0.0f) ? c : 0.0f;
}

// clipped length fraction only
__device__ __forceinline__ float clip_dt(
    float u0, float ru, float v0, float rv, float hu, float hv)
{
    float t0, t1;
    clip_window(u0, ru, v0, rv, hu, hv, t0, t1);
    return fmaxf(t1 - t0, 0.0f);
}

__device__ __forceinline__ float ciou_one(const float* __restrict__ pred,
                                          const float* __restrict__ target,
                                          const float* __restrict__ weight,
                                          int i)
{
    const float* P = pred   + (size_t)i * 5;
    const float* T = target + (size_t)i * 5;
    float px = P[0], py = P[1], pw = P[2], ph = P[3], pa = P[4];
    float qx = T[0], qy = T[1], qw = T[2], qh = T[3], qa = T[4];
    float w  = weight[i];

    float ox = qx - px, oy = qy - py;

    float cp, sp, cq, sq;
    __sincosf(pa, &sp, &cp);
    __sincosf(qa, &sq, &cq);
    float hw1 = 0.5f * pw, hh1 = 0.5f * ph;
    float hw2 = 0.5f * qw, hh2 = 0.5f * qh;

    // relative rotation r = pa - qa
    float cr = fmaf(cp, cq,  sp * sq);
    float sr = fmaf(sp, cq, -cp * sq);

    // frame offsets
    float eu = fmaf(ox, cp,  oy * sp);       // box2 center in box1 frame
    float ev = fmaf(-ox, sp, oy * cp);
    float du_ = -fmaf(ox, cq,  oy * sq);     // box1 center in box2 frame
    float dv_ =  fmaf(ox, sq, -oy * cq);

    // half-extent projections
    float E = cr * hw2, F = sr * hh2, G = sr * hw2, H = cr * hh2;
    float A = cr * hw1, B = sr * hh1, C = sr * hw1, D = cr * hh1;

    // shared reciprocals of edge deltas (sign-symmetric RCP: negate for
    // the antiparallel opposite edge)
    float E2 = E + E, F2 = F + F, G2 = G + G, H2 = H + H;
    float B2 = B + B, D2 = D + D;
    float rE = __fdividef(1.0f, E2);
    float rF = __fdividef(1.0f, F2);
    float rG = __fdividef(1.0f, G2);
    float rH = __fdividef(1.0f, H2);
    float rB = __fdividef(1.0f, B2);
    float rD = __fdividef(1.0f, D2);

    // box2 corners in box1's frame (CCW)
    float tu0 =  E + F + eu, tv0 = -G + H + ev;
    float tu1 = -E + F + eu, tv1 =  G + H + ev;
    float tu2 = -E - F + eu, tv2 =  G - H + ev;
    float tu3 =  E - F + eu, tv3 = -G - H + ev;

    // box1 corners 1 and 3 in box2's frame (starts of its vertical edges)
    float su1 = -A - B + du_, sv1 = -C + D + dv_;
    float su3 =  A + B + du_, sv3 =  C - D + dv_;

    // Green's theorem in box1's frame: box2's 4 edges (deltas: e01=(-2E,2G),
    // e12=(-2F,-2H), e23=(2E,-2G), e30=(2F,2H)), clipped to |u|<=hw1,|v|<=hh1
    float area;
    area  = clip_integral(tu0, -E2, -rE, tv0,  G2,  rG, hw1, hh1);
    area += clip_integral(tu1, -F2, -rF, tv1, -H2, -rH, hw1, hh1);
    area += clip_integral(tu2,  E2,  rE, tv2, -G2, -rG, hw1, hh1);
    area += clip_integral(tu3,  F2,  rF, tv3,  H2,  rH, hw1, hh1);

    // box1's vertical edges: e12=(2B,-2D) from corner1, e30=(-2B,2D) from
    // corner3, clipped to box2; each contributes 2*hw1*hh1*dt
    float dt13 = clip_dt(su1,  rB, sv1, -rD, hw2, hh2)
               + clip_dt(su3, -rB, sv3,  rD, hw2, hh2);
    area = fmaf(2.0f * hw1 * hh1, dt13, area);

    float inter = fabsf(area);

    // CIoU loss
    float a1 = pw * ph;
    float a2 = qw * qh;
    float ious = fmaxf(__fdividef(inter, a1 + a2 - inter), EPSF);
    float cd = fmaf(ox, ox, oy * oy);

    // atan(qw/(qh+e)) - atan(pw/(ph+e)) = atan(num/den); only da^2 used
    float num = fmaf(qw, ph + EPSF, -pw * (qh + EPSF));
    float den = fmaf(qh + EPSF, ph + EPSF, qw * pw);
    float da = fast_atan_pos(fabsf(__fdividef(num, den)));
    float aspect = 0.40528473456935109f * da * da;   // 4/pi^2

    float omi = 1.0f - ious;
    float vterm = __fdividef(aspect, omi + aspect);
    float alpha = __fdividef(vterm, omi + vterm);
    float loss = omi + __fdividef(cd, fmaf(pw, pw, ph * ph) + EPSF)
               + alpha * vterm;
    return loss * w;
}

__global__ void __launch_bounds__(THREADS) k_ciou(const float* __restrict__ pred,
                                                  const float* __restrict__ target,
                                                  const float* __restrict__ weight,
                                                  float* __restrict__ out,
                                                  int N)
{
    int base = blockIdx.x * (THREADS * BOXES_PER_THREAD);
    float contrib = 0.0f;

    #pragma unroll
    for (int s = 0; s < BOXES_PER_THREAD; s++) {
        int i = base + s * THREADS + threadIdx.x;
        if (i < N)
            contrib += ciou_one(pred, target, weight, i);
    }

    // ---- block reduction ----
    #pragma unroll
    for (int o = 16; o > 0; o >>= 1)
        contrib += __shfl_down_sync(0xffffffffu, contrib, o);

    __shared__ float ws[THREADS / 32];
    __shared__ bool is_last;
    int lane = threadIdx.x & 31;
    int wid  = threadIdx.x >> 5;
    if (lane == 0) ws[wid] = contrib;
    __syncthreads();
    if (wid == 0) {
        float s = (lane < THREADS / 32) ? ws[lane] : 0.0f;
        #pragma unroll
        for (int o = 4; o > 0; o >>= 1)
            s += __shfl_down_sync(0xffu, s, o);
        if (lane == 0) {
            g_partial[blockIdx.x] = s;
            __threadfence();
            unsigned int t = atomicAdd(&g_done, 1u);
            is_last = (t == gridDim.x - 1);
        }
    }
    __syncthreads();

    // ---- last block: reduce partials, write mean, reset counter ----
    if (is_last) {
        int nblocks = gridDim.x;
        double acc = 0.0;
        for (int k = threadIdx.x; k < nblocks; k += THREADS)
            acc += (double)g_partial[k];

        #pragma unroll
        for (int o = 16; o > 0; o >>= 1)
            acc += __shfl_down_sync(0xffffffffu, acc, o);

        __shared__ double wd[THREADS / 32];
        if (lane == 0) wd[wid] = acc;
        __syncthreads();
        if (wid == 0) {
            double s = (lane < THREADS / 32) ? wd[lane] : 0.0;
            #pragma unroll
            for (int o = 4; o > 0; o >>= 1)
                s += __shfl_down_sync(0xffu, s, o);
            if (lane == 0) {
                out[0] = (float)(s / (double)N);
                g_done = 0;
            }
        }
    }
}

extern "C" void kernel_launch(void* const* d_in, const int* in_sizes, int n_in,
                              void* d_out, int out_size)
{
    const float* pred   = (const float*)d_in[0];
    const float* target = (const float*)d_in[1];
    const float* weight = (const float*)d_in[2];
    int N = in_sizes[2];

    int per_block = THREADS * BOXES_PER_THREAD;
    int blocks = (N + per_block - 1) / per_block;
    k_ciou<<<blocks, THREADS>>>(pred, target, weight, (float*)d_out, N);
}